// round 6
// baseline (speedup 1.0000x reference)
#include <cuda_runtime.h>
#include <cuda_bf16.h>
#include <math.h>
#include <stdint.h>

constexpr int BB = 2048, TT = 64, SS = 64, AA = 16, HH = 512, RR = 512, EE = 1024;

// ---------------- device scratch ----------------
__device__ float g_gh  [BB * 3 * RR];
__device__ float g_bel [BB * RR];
__device__ float g_qpart[4 * BB * 128];
__device__ float g_qpre   [(size_t)BB * TT * HH];
__device__ float g_act_pre[(size_t)BB * TT * HH];
__device__ float g_pall   [(size_t)BB * TT * 2 * SS];

__device__ __nv_bfloat16 g_obs_split[(size_t)BB * TT * 2 * EE];  // reused as h1_split
__device__ __nv_bfloat16 g_bel_all  [(size_t)BB * TT * 2 * RR];
__device__ __nv_bfloat16 g_act_pad  [(size_t)BB * TT * 64];
__device__ __nv_bfloat16 g_x_split  [BB * 2 * HH];
__device__ __nv_bfloat16 g_bel_split[BB * 2 * RR];
__device__ __nv_bfloat16 g_h2_split [BB * 2 * HH];
__device__ __nv_bfloat16 g_post_split[BB * 128];

// Pre-split weights: [N x K3pad] bf16, segments [Wh | Wh | Wl]
__device__ __nv_bfloat16 w_as1[512 * 192];
__device__ __nv_bfloat16 w_as2[512 * 64];
__device__ __nv_bfloat16 w_ih [1536 * 1536];
__device__ __nv_bfloat16 w_hh [1536 * 1536];
__device__ __nv_bfloat16 w_p1 [512 * 1536];
__device__ __nv_bfloat16 w_p2 [128 * 1536];
__device__ __nv_bfloat16 w_q1r[512 * 1536];
__device__ __nv_bfloat16 w_q1o[512 * 3072];
__device__ __nv_bfloat16 w_q2 [128 * 1536];

// ---------------- helpers ----------------
__device__ __forceinline__ uint32_t smem_u32(const void* p) {
    uint32_t a;
    asm("{ .reg .u64 t; cvta.to.shared.u64 t, %1; cvt.u32.u64 %0, t; }" : "=r"(a) : "l"(p));
    return a;
}
__device__ __forceinline__ void ldmatrix_x4(uint32_t* r, uint32_t addr) {
    asm volatile("ldmatrix.sync.aligned.m8n8.x4.shared.b16 {%0,%1,%2,%3}, [%4];"
                 : "=r"(r[0]), "=r"(r[1]), "=r"(r[2]), "=r"(r[3]) : "r"(addr));
}
__device__ __forceinline__ void mma_16816(float* d, const uint32_t* a,
                                          uint32_t b0, uint32_t b1) {
    asm volatile(
        "mma.sync.aligned.m16n8k16.row.col.f32.bf16.bf16.f32 "
        "{%0,%1,%2,%3}, {%4,%5,%6,%7}, {%8,%9}, {%0,%1,%2,%3};"
        : "+f"(d[0]), "+f"(d[1]), "+f"(d[2]), "+f"(d[3])
        : "r"(a[0]), "r"(a[1]), "r"(a[2]), "r"(a[3]), "r"(b0), "r"(b1));
}
__device__ __forceinline__ void cp16(uint32_t s, const void* g) {
    asm volatile("cp.async.cg.shared.global [%0], [%1], 16;" :: "r"(s), "l"(g));
}
#define CP_COMMIT() asm volatile("cp.async.commit_group;" ::: "memory")

__device__ __forceinline__ void split2(float v, __nv_bfloat16& hi, __nv_bfloat16& lo) {
    hi = __float2bfloat16(v);
    lo = __float2bfloat16(v - __bfloat162float(hi));
}
__device__ __forceinline__ float sigmoidf_(float x) { return 1.f / (1.f + expf(-x)); }

// ---------------- GEMM problem descriptor ----------------
struct GProb {
    const __nv_bfloat16* A; int lda; int Kseg; int KT;
    const __nv_bfloat16* B; int ldb;
    const float* bias; const float* addm; int ldadd;
    float* C; int ldc;
    __nv_bfloat16* Cs; int Ntot;
    int act;
    int ktz;
    int cstride;
};

__global__ __launch_bounds__(256)
void tgemm(GProb p0, GProb p1, int nx0)
{
    GProb p; int bx = blockIdx.x;
    if (bx < nx0) p = p0; else { p = p1; bx -= nx0; }

    __shared__ __align__(1024) unsigned char sm[49152];
    const uint32_t smA = smem_u32(sm);
    const uint32_t smB = smA + 32768;

    const int tid = threadIdx.x, lane = tid & 31, wid = tid >> 5;
    const int wm = wid >> 1, wn = wid & 1;
    const int m0 = blockIdx.y * 128, n0 = bx * 64;
    const int K2 = 2 * p.Kseg;

    int ktb = 0, kte = p.KT;
    float* Cout = p.C;
    if (p.ktz > 0) {
        ktb = blockIdx.z * p.ktz; kte = ktb + p.ktz;
        Cout = p.C + (size_t)blockIdx.z * p.cstride;
    }

    float acc[2][4][4];
#pragma unroll
    for (int i = 0; i < 2; i++)
#pragma unroll
        for (int j = 0; j < 4; j++)
#pragma unroll
            for (int q = 0; q < 4; q++) acc[i][j][q] = 0.f;

    auto stage = [&](int kt, int buf) {
        int k0 = kt * 64;
        int k0e = (k0 >= K2) ? k0 - K2 : k0;
        uint32_t dA = smA + buf * 16384, dB = smB + buf * 8192;
#pragma unroll
        for (int it = 0; it < 4; ++it) {
            int idx = tid + it * 256, row = idx >> 3, c = idx & 7;
            cp16(dA + row * 128 + ((c ^ (row & 7)) * 16),
                 p.A + (size_t)(m0 + row) * p.lda + k0e + c * 8);
        }
#pragma unroll
        for (int it = 0; it < 2; ++it) {
            int idx = tid + it * 256, row = idx >> 3, c = idx & 7;
            cp16(dB + row * 128 + ((c ^ (row & 7)) * 16),
                 p.B + (size_t)(n0 + row) * p.ldb + kt * 64 + c * 8);
        }
        CP_COMMIT();
    };

    stage(ktb, 0);
    for (int kt = ktb; kt < kte; ++kt) {
        const int buf = (kt - ktb) & 1;
        const bool more = (kt + 1 < kte);
        if (more) stage(kt + 1, 1 - buf);
        if (more) asm volatile("cp.async.wait_group 1;" ::: "memory");
        else      asm volatile("cp.async.wait_group 0;" ::: "memory");
        __syncthreads();

        const uint32_t baseA = smA + buf * 16384;
        const uint32_t baseB = smB + buf * 8192;
#pragma unroll
        for (int ks = 0; ks < 4; ++ks) {
            uint32_t a[2][4], bq[2][4];
#pragma unroll
            for (int mt = 0; mt < 2; ++mt) {
                int row = wm * 32 + mt * 16 + (lane & 15);
                int kc = ks * 2 + (lane >> 4);
                ldmatrix_x4(a[mt], baseA + row * 128 + ((kc ^ (row & 7)) * 16));
            }
#pragma unroll
            for (int nb = 0; nb < 2; ++nb) {
                int row = wn * 32 + nb * 16 + (lane & 15);
                int kc = ks * 2 + (lane >> 4);
                ldmatrix_x4(bq[nb], baseB + row * 128 + ((kc ^ (row & 7)) * 16));
            }
#pragma unroll
            for (int mt = 0; mt < 2; ++mt) {
                mma_16816(acc[mt][0], a[mt], bq[0][0], bq[0][2]);
                mma_16816(acc[mt][1], a[mt], bq[0][1], bq[0][3]);
                mma_16816(acc[mt][2], a[mt], bq[1][0], bq[1][2]);
                mma_16816(acc[mt][3], a[mt], bq[1][1], bq[1][3]);
            }
        }
        __syncthreads();
    }

    const int mbase = m0 + wm * 32;
    const int nbase = n0 + wn * 32;
#pragma unroll
    for (int mt = 0; mt < 2; ++mt) {
#pragma unroll
        for (int nt = 0; nt < 4; ++nt) {
            int col = nbase + nt * 8 + 2 * (lane & 3);
            float bxv = 0.f, byv = 0.f;
            if (p.bias) { bxv = p.bias[col]; byv = p.bias[col + 1]; }
#pragma unroll
            for (int h = 0; h < 2; ++h) {
                int row = mbase + mt * 16 + (lane >> 2) + h * 8;
                float vx = acc[mt][nt][2 * h + 0] + bxv;
                float vy = acc[mt][nt][2 * h + 1] + byv;
                if (p.addm) {
                    const float* ap = p.addm + (size_t)row * p.ldadd + col;
                    vx += ap[0]; vy += ap[1];
                }
                if (p.act == 1) {
                    vx = vx > 0.f ? vx : expm1f(vx);
                    vy = vy > 0.f ? vy : expm1f(vy);
                }
                if (p.Cs) {
                    __nv_bfloat16 hx, lx, hy, ly;
                    split2(vx, hx, lx); split2(vy, hy, ly);
                    size_t base = (size_t)row * (2 * p.Ntot);
                    *reinterpret_cast<__nv_bfloat162*>(&p.Cs[base + col]) =
                        __nv_bfloat162(hx, hy);
                    *reinterpret_cast<__nv_bfloat162*>(&p.Cs[base + p.Ntot + col]) =
                        __nv_bfloat162(lx, ly);
                } else {
                    *reinterpret_cast<float2*>(&Cout[(size_t)row * p.ldc + col]) =
                        make_float2(vx, vy);
                }
            }
        }
    }
}

// ---------------- fused gi GEMM (3 gates per CTA) + GRU epilogue ----------------
// grid (8,16). CTA covers rows m0=by*128 and r-block jr=bx*64 for all 3 gates.
__global__ __launch_bounds__(256)
void gi_gru(const __nv_bfloat16* __restrict__ Axs,   // x_split [2048 x 1024]
            const __nv_bfloat16* __restrict__ Wih,   // [1536 x 1536]
            const float* __restrict__ bih,
            float* __restrict__ out_bel, int t)
{
    extern __shared__ __align__(1024) unsigned char sm[];
    const uint32_t smA = smem_u32(sm);            // 2 x 16KB
    const uint32_t smB = smA + 32768;             // (buf*3+g) * 8KB, 6 x 8KB

    const int tid = threadIdx.x, lane = tid & 31, wid = tid >> 5;
    const int wm = wid >> 1, wn = wid & 1;
    const int m0 = blockIdx.y * 128, jr = blockIdx.x * 64;

    float acc[3][2][4][4];
#pragma unroll
    for (int g = 0; g < 3; g++)
#pragma unroll
        for (int i = 0; i < 2; i++)
#pragma unroll
            for (int j = 0; j < 4; j++)
#pragma unroll
                for (int q = 0; q < 4; q++) acc[g][i][j][q] = 0.f;

    auto stage = [&](int kt, int buf) {
        int k0 = kt * 64;
        int k0e = (k0 >= 1024) ? k0 - 1024 : k0;
#pragma unroll
        for (int it = 0; it < 4; ++it) {
            int idx = tid + it * 256, row = idx >> 3, c = idx & 7;
            cp16(smA + buf * 16384 + row * 128 + ((c ^ (row & 7)) * 16),
                 Axs + (size_t)(m0 + row) * 1024 + k0e + c * 8);
        }
#pragma unroll
        for (int g = 0; g < 3; ++g) {
            const __nv_bfloat16* Bg = Wih + (size_t)(g * 512 + jr) * 1536;
#pragma unroll
            for (int it = 0; it < 2; ++it) {
                int idx = tid + it * 256, row = idx >> 3, c = idx & 7;
                cp16(smB + (buf * 3 + g) * 8192 + row * 128 + ((c ^ (row & 7)) * 16),
                     Bg + (size_t)row * 1536 + k0 + c * 8);
            }
        }
        CP_COMMIT();
    };

    stage(0, 0);
    for (int kt = 0; kt < 24; ++kt) {
        const int buf = kt & 1;
        const bool more = (kt + 1 < 24);
        if (more) stage(kt + 1, 1 - buf);
        if (more) asm volatile("cp.async.wait_group 1;" ::: "memory");
        else      asm volatile("cp.async.wait_group 0;" ::: "memory");
        __syncthreads();

        const uint32_t baseA = smA + buf * 16384;
#pragma unroll
        for (int ks = 0; ks < 4; ++ks) {
            uint32_t a[2][4];
#pragma unroll
            for (int mt = 0; mt < 2; ++mt) {
                int row = wm * 32 + mt * 16 + (lane & 15);
                int kc = ks * 2 + (lane >> 4);
                ldmatrix_x4(a[mt], baseA + row * 128 + ((kc ^ (row & 7)) * 16));
            }
#pragma unroll
            for (int g = 0; g < 3; ++g) {
                const uint32_t baseB = smB + (buf * 3 + g) * 8192;
                uint32_t bq[2][4];
#pragma unroll
                for (int nb = 0; nb < 2; ++nb) {
                    int row = wn * 32 + nb * 16 + (lane & 15);
                    int kc = ks * 2 + (lane >> 4);
                    ldmatrix_x4(bq[nb], baseB + row * 128 + ((kc ^ (row & 7)) * 16));
                }
#pragma unroll
                for (int mt = 0; mt < 2; ++mt) {
                    mma_16816(acc[g][mt][0], a[mt], bq[0][0], bq[0][2]);
                    mma_16816(acc[g][mt][1], a[mt], bq[0][1], bq[0][3]);
                    mma_16816(acc[g][mt][2], a[mt], bq[1][0], bq[1][2]);
                    mma_16816(acc[g][mt][3], a[mt], bq[1][1], bq[1][3]);
                }
            }
        }
        __syncthreads();
    }

    // ---- GRU epilogue ----
    const int mbase = m0 + wm * 32;
    const int nbase = wn * 32;
#pragma unroll
    for (int mt = 0; mt < 2; ++mt) {
#pragma unroll
        for (int nt = 0; nt < 4; ++nt) {
            int col = nbase + nt * 8 + 2 * (lane & 3);
            int r = jr + col;
            float2 br = *reinterpret_cast<const float2*>(&bih[r]);
            float2 bz = *reinterpret_cast<const float2*>(&bih[512 + r]);
            float2 bn_ = *reinterpret_cast<const float2*>(&bih[1024 + r]);
#pragma unroll
            for (int h = 0; h < 2; ++h) {
                int row = mbase + mt * 16 + (lane >> 2) + h * 8;
                float2 ghr = *reinterpret_cast<const float2*>(&g_gh[(size_t)row * 1536 + r]);
                float2 ghz = *reinterpret_cast<const float2*>(&g_gh[(size_t)row * 1536 + 512 + r]);
                float2 ghn = *reinterpret_cast<const float2*>(&g_gh[(size_t)row * 1536 + 1024 + r]);
                float2 bo  = *reinterpret_cast<const float2*>(&g_bel[(size_t)row * 512 + r]);
                float gix = acc[0][mt][nt][2 * h + 0] + br.x;
                float giy = acc[0][mt][nt][2 * h + 1] + br.y;
                float gzx = acc[1][mt][nt][2 * h + 0] + bz.x;
                float gzy = acc[1][mt][nt][2 * h + 1] + bz.y;
                float gnx = acc[2][mt][nt][2 * h + 0] + bn_.x;
                float gny = acc[2][mt][nt][2 * h + 1] + bn_.y;
                float rgx = sigmoidf_(gix + ghr.x), rgy = sigmoidf_(giy + ghr.y);
                float zgx = sigmoidf_(gzx + ghz.x), zgy = sigmoidf_(gzy + ghz.y);
                float nnx = tanhf(gnx + rgx * ghn.x), nny = tanhf(gny + rgy * ghn.y);
                float bnx = (1.f - zgx) * nnx + zgx * bo.x;
                float bny = (1.f - zgy) * nny + zgy * bo.y;
                *reinterpret_cast<float2*>(&g_bel[(size_t)row * 512 + r]) =
                    make_float2(bnx, bny);
                *reinterpret_cast<float2*>(&out_bel[((size_t)row * TT + t) * 512 + r]) =
                    make_float2(bnx, bny);
                __nv_bfloat16 hx, lx, hy, ly;
                split2(bnx, hx, lx); split2(bny, hy, ly);
                *reinterpret_cast<__nv_bfloat162*>(&g_bel_split[(size_t)row * 1024 + r]) =
                    __nv_bfloat162(hx, hy);
                *reinterpret_cast<__nv_bfloat162*>(&g_bel_split[(size_t)row * 1024 + 512 + r]) =
                    __nv_bfloat162(lx, ly);
                size_t ra = ((size_t)row * TT + t) * 1024;
                *reinterpret_cast<__nv_bfloat162*>(&g_bel_all[ra + r]) =
                    __nv_bfloat162(hx, hy);
                *reinterpret_cast<__nv_bfloat162*>(&g_bel_all[ra + 512 + r]) =
                    __nv_bfloat162(lx, ly);
            }
        }
    }
}

// ---------------- fused q-reduce + dist_q + x(t+1) GEMM ----------------
// grid (8,16). Phase 1: reduce split-K q partials, distribution, post -> smem
// bf16 tiles. Phase 2: x(t+1) = elu(post @ W_as1 + act_pre(t+1)) -> x_split.
__global__ __launch_bounds__(256)
void qdx(const float* __restrict__ noise_q, const float* __restrict__ bq2,
         const __nv_bfloat16* __restrict__ Was1,
         const float* __restrict__ actpre_t1,
         float* __restrict__ o_mean, float* __restrict__ o_std,
         float* __restrict__ o_state, int t, int do_x)
{
    __shared__ __align__(1024) unsigned char sm[49152];  // A hi 16K | A lo 16K | B 2x8K
    const uint32_t smA = smem_u32(sm);
    const uint32_t smB = smA + 32768;

    const int tid = threadIdx.x, lane = tid & 31, wid = tid >> 5;
    const int wm = wid >> 1, wn = wid & 1;
    const int m0 = blockIdx.y * 128, n0 = blockIdx.x * 64;

    // ---- phase 1 ----
    for (int idx = tid; idx < 128 * 64; idx += 256) {
        int row = idx >> 6, s = idx & 63;
        int b = m0 + row;
        float m = bq2[s], raw = bq2[64 + s];
#pragma unroll
        for (int z = 0; z < 4; ++z) {
            m   += g_qpart[(size_t)z * BB * 128 + b * 128 + s];
            raw += g_qpart[(size_t)z * BB * 128 + b * 128 + 64 + s];
        }
        float sp = raw > 20.f ? raw : log1pf(expf(raw));
        float sd = sp + 0.1f;
        float eps = noise_q[((size_t)b * TT + t) * 64 + s];
        float st = m + sd * eps;
        if (blockIdx.x == 0) {
            size_t o = ((size_t)b * TT + t) * 64 + s;
            o_mean[o] = m; o_std[o] = sd; o_state[o] = st;
        }
        __nv_bfloat16 hi, lo;
        split2(st, hi, lo);
        int c = s >> 3, off = (s & 7) * 2;
        *reinterpret_cast<uint16_t*>(sm + row * 128 + ((c ^ (row & 7)) * 16) + off) =
            __bfloat16_as_ushort(hi);
        *reinterpret_cast<uint16_t*>(sm + 16384 + row * 128 + ((c ^ (row & 7)) * 16) + off) =
            __bfloat16_as_ushort(lo);
    }
    __syncthreads();
    if (!do_x) return;

    // ---- phase 2: KT=3 (A tiles hi, lo, hi) ----
    float acc[2][4][4];
#pragma unroll
    for (int i = 0; i < 2; i++)
#pragma unroll
        for (int j = 0; j < 4; j++)
#pragma unroll
            for (int q = 0; q < 4; q++) acc[i][j][q] = 0.f;

    auto stageB = [&](int kt, int buf) {
#pragma unroll
        for (int it = 0; it < 2; ++it) {
            int idx = tid + it * 256, row = idx >> 3, c = idx & 7;
            cp16(smB + buf * 8192 + row * 128 + ((c ^ (row & 7)) * 16),
                 Was1 + (size_t)(n0 + row) * 192 + kt * 64 + c * 8);
        }
        CP_COMMIT();
    };

    stageB(0, 0);
    for (int kt = 0; kt < 3; ++kt) {
        const int buf = kt & 1;
        const bool more = (kt + 1 < 3);
        if (more) stageB(kt + 1, 1 - buf);
        if (more) asm volatile("cp.async.wait_group 1;" ::: "memory");
        else      asm volatile("cp.async.wait_group 0;" ::: "memory");
        __syncthreads();

        const uint32_t baseA = smA + ((kt == 1) ? 16384 : 0);
        const uint32_t baseB = smB + buf * 8192;
#pragma unroll
        for (int ks = 0; ks < 4; ++ks) {
            uint32_t a[2][4], bq[2][4];
#pragma unroll
            for (int mt = 0; mt < 2; ++mt) {
                int row = wm * 32 + mt * 16 + (lane & 15);
                int kc = ks * 2 + (lane >> 4);
                ldmatrix_x4(a[mt], baseA + row * 128 + ((kc ^ (row & 7)) * 16));
            }
#pragma unroll
            for (int nb = 0; nb < 2; ++nb) {
                int row = wn * 32 + nb * 16 + (lane & 15);
                int kc = ks * 2 + (lane >> 4);
                ldmatrix_x4(bq[nb], baseB + row * 128 + ((kc ^ (row & 7)) * 16));
            }
#pragma unroll
            for (int mt = 0; mt < 2; ++mt) {
                mma_16816(acc[mt][0], a[mt], bq[0][0], bq[0][2]);
                mma_16816(acc[mt][1], a[mt], bq[0][1], bq[0][3]);
                mma_16816(acc[mt][2], a[mt], bq[1][0], bq[1][2]);
                mma_16816(acc[mt][3], a[mt], bq[1][1], bq[1][3]);
            }
        }
        __syncthreads();
    }

    const int mbase = m0 + wm * 32;
    const int nbase = n0 + wn * 32;
#pragma unroll
    for (int mt = 0; mt < 2; ++mt) {
#pragma unroll
        for (int nt = 0; nt < 4; ++nt) {
            int col = nbase + nt * 8 + 2 * (lane & 3);
#pragma unroll
            for (int h = 0; h < 2; ++h) {
                int row = mbase + mt * 16 + (lane >> 2) + h * 8;
                const float* ap = actpre_t1 + (size_t)row * (TT * HH) + col;
                float vx = acc[mt][nt][2 * h + 0] + ap[0];
                float vy = acc[mt][nt][2 * h + 1] + ap[1];
                vx = vx > 0.f ? vx : expm1f(vx);
                vy = vy > 0.f ? vy : expm1f(vy);
                __nv_bfloat16 hx, lx, hy, ly;
                split2(vx, hx, lx); split2(vy, hy, ly);
                size_t base = (size_t)row * 1024;
                *reinterpret_cast<__nv_bfloat162*>(&g_x_split[base + col]) =
                    __nv_bfloat162(hx, hy);
                *reinterpret_cast<__nv_bfloat162*>(&g_x_split[base + 512 + col]) =
                    __nv_bfloat162(lx, ly);
            }
        }
    }
}

// ---------------- weight prep ----------------
__global__ void prep_w(const float* __restrict__ src, int K, int N, int K3pad,
                       int transpose, __nv_bfloat16* __restrict__ dst)
{
    int idx = blockIdx.x * blockDim.x + threadIdx.x;
    if (idx >= N * K3pad) return;
    int n = idx / K3pad, k3 = idx % K3pad;
    __nv_bfloat16 out;
    if (k3 >= 3 * K) out = __float2bfloat16(0.f);
    else {
        int seg = k3 / K, kk = k3 % K;
        float v = transpose ? src[(size_t)kk * N + n] : src[(size_t)n * K + kk];
        __nv_bfloat16 hi = __float2bfloat16(v);
        out = (seg < 2) ? hi : __float2bfloat16(v - __bfloat162float(hi));
    }
    dst[idx] = out;
}

__global__ void split_act(const float* __restrict__ src, __nv_bfloat16* __restrict__ dst,
                          long total, int K)
{
    long idx = (long)blockIdx.x * blockDim.x + threadIdx.x;
    if (idx >= total) return;
    long r = idx / K; int k = (int)(idx % K);
    __nv_bfloat16 hi, lo;
    split2(src[idx], hi, lo);
    dst[r * (2 * K) + k] = hi;
    dst[r * (2 * K) + K + k] = lo;
}

__global__ void act_split_pad(const float* __restrict__ a)
{
    int idx = blockIdx.x * blockDim.x + threadIdx.x;
    if (idx >= BB * TT * AA) return;
    int bt = idx >> 4, k = idx & 15;
    __nv_bfloat16 hi, lo;
    split2(a[idx], hi, lo);
    __nv_bfloat16* d = g_act_pad + (size_t)bt * 64;
    d[k] = hi; d[16 + k] = lo; d[32 + k] = hi; d[48 + k] = __float2bfloat16(0.f);
}

__global__ void init_state(const float* __restrict__ bel0, const float* __restrict__ post0)
{
    int i = blockIdx.x * blockDim.x + threadIdx.x;
    if (i < BB * SS) {
        int b = i >> 6, s = i & 63;
        __nv_bfloat16 hi, lo;
        split2(post0[i], hi, lo);
        g_post_split[b * 128 + s] = hi;
        g_post_split[b * 128 + 64 + s] = lo;
    }
    if (i < BB * RR) {
        float v = bel0[i];
        g_bel[i] = v;
        int b = i >> 9, r = i & 511;
        __nv_bfloat16 hi, lo;
        split2(v, hi, lo);
        g_bel_split[b * 1024 + r] = hi;
        g_bel_split[b * 1024 + 512 + r] = lo;
    }
}

__global__ void dist_p_kernel(const float* __restrict__ noise,
                              float* __restrict__ o_mean, float* __restrict__ o_std,
                              float* __restrict__ o_state)
{
    int idx = blockIdx.x * blockDim.x + threadIdx.x;
    if (idx >= BB * TT * SS) return;
    int s = idx & 63;
    int bt = idx >> 6;
    float m   = g_pall[(size_t)bt * (2 * SS) + s];
    float raw = g_pall[(size_t)bt * (2 * SS) + SS + s];
    float sp = raw > 20.f ? raw : log1pf(expf(raw));
    float sd = sp + 0.1f;
    float st = m + sd * noise[idx];
    o_mean[idx] = m; o_std[idx] = sd; o_state[idx] = st;
}

// ---------------- launch ----------------
static GProb mkprob(const __nv_bfloat16* A, int lda, int Kseg, int KT,
                    const __nv_bfloat16* B, int ldb,
                    const float* bias, const float* addm, int ldadd,
                    float* C, int ldc, __nv_bfloat16* Cs, int Ntot, int act,
                    int ktz = 0, int cstride = 0)
{
    GProb p{A, lda, Kseg, KT, B, ldb, bias, addm, ldadd, C, ldc, Cs, Ntot, act,
            ktz, cstride};
    return p;
}

extern "C" void kernel_launch(void* const* d_in, const int* in_sizes, int n_in,
                              void* d_out, int out_size)
{
    const float* posterior = (const float*)d_in[0];
    const float* belief    = (const float*)d_in[1];
    const float* actions   = (const float*)d_in[2];
    const float* obs       = (const float*)d_in[3];
    const float* noise_p   = (const float*)d_in[4];
    const float* noise_q   = (const float*)d_in[5];
    const float* W_as = (const float*)d_in[6];
    const float* b_as = (const float*)d_in[7];
    const float* W_ih = (const float*)d_in[8];
    const float* b_ih = (const float*)d_in[9];
    const float* W_hh = (const float*)d_in[10];
    const float* b_hh = (const float*)d_in[11];
    const float* W_p1 = (const float*)d_in[12];
    const float* b_p1 = (const float*)d_in[13];
    const float* W_p2 = (const float*)d_in[14];
    const float* b_p2 = (const float*)d_in[15];
    const float* W_q1 = (const float*)d_in[16];
    const float* b_q1 = (const float*)d_in[17];
    const float* W_q2 = (const float*)d_in[18];
    const float* b_q2 = (const float*)d_in[19];

    float *pgh, *pqpre, *pactpre, *ppall, *pqpart;
    __nv_bfloat16 *pobs, *pbela, *pactpad, *pxs, *pbels, *ph2s, *pposts;
    __nv_bfloat16 *pw_as1, *pw_as2, *pw_ih, *pw_hh, *pw_p1, *pw_p2, *pw_q1r, *pw_q1o, *pw_q2;
    cudaGetSymbolAddress((void**)&pgh,     g_gh);
    cudaGetSymbolAddress((void**)&pqpre,   g_qpre);
    cudaGetSymbolAddress((void**)&pactpre, g_act_pre);
    cudaGetSymbolAddress((void**)&ppall,   g_pall);
    cudaGetSymbolAddress((void**)&pqpart,  g_qpart);
    cudaGetSymbolAddress((void**)&pobs,    g_obs_split);
    cudaGetSymbolAddress((void**)&pbela,   g_bel_all);
    cudaGetSymbolAddress((void**)&pactpad, g_act_pad);
    cudaGetSymbolAddress((void**)&pxs,     g_x_split);
    cudaGetSymbolAddress((void**)&pbels,   g_bel_split);
    cudaGetSymbolAddress((void**)&ph2s,    g_h2_split);
    cudaGetSymbolAddress((void**)&pposts,  g_post_split);
    cudaGetSymbolAddress((void**)&pw_as1,  w_as1);
    cudaGetSymbolAddress((void**)&pw_as2,  w_as2);
    cudaGetSymbolAddress((void**)&pw_ih,   w_ih);
    cudaGetSymbolAddress((void**)&pw_hh,   w_hh);
    cudaGetSymbolAddress((void**)&pw_p1,   w_p1);
    cudaGetSymbolAddress((void**)&pw_p2,   w_p2);
    cudaGetSymbolAddress((void**)&pw_q1r,  w_q1r);
    cudaGetSymbolAddress((void**)&pw_q1o,  w_q1o);
    cudaGetSymbolAddress((void**)&pw_q2,   w_q2);

    cudaFuncSetAttribute(gi_gru, cudaFuncAttributeMaxDynamicSharedMemorySize, 81920);

    float* out = (float*)d_out;
    const size_t BT = (size_t)BB * TT;
    float* o_pmean = out;
    float* o_pstd  = out + BT * SS;
    float* o_prior = out + 2 * BT * SS;
    float* o_bel   = out + 3 * BT * SS;
    float* o_qmean = out + 3 * BT * SS + BT * RR;
    float* o_qstd  = o_qmean + BT * SS;
    float* o_post  = o_qstd  + BT * SS;

    init_state<<<(BB * RR + 255) / 256, 256>>>(belief, posterior);

    auto prep = [](const float* src, int K, int N, int K3pad, int tr, __nv_bfloat16* dst) {
        int n = N * K3pad;
        prep_w<<<(n + 255) / 256, 256>>>(src, K, N, K3pad, tr, dst);
    };
    prep(W_as,              64,  512,  192, 1, pw_as1);
    prep(W_as + 64 * 512,   16,  512,   64, 1, pw_as2);
    prep(W_ih,             512, 1536, 1536, 0, pw_ih);
    prep(W_hh,             512, 1536, 1536, 0, pw_hh);
    prep(W_p1,             512,  512, 1536, 1, pw_p1);
    prep(W_p2,             512,  128, 1536, 1, pw_p2);
    prep(W_q1,             512,  512, 1536, 1, pw_q1r);
    prep(W_q1 + 512 * 512, 1024, 512, 3072, 1, pw_q1o);
    prep(W_q2,             512,  128, 1536, 1, pw_q2);

    {
        long total = (long)BT * EE;
        split_act<<<(unsigned)((total + 255) / 256), 256>>>(obs, pobs, total, EE);
        act_split_pad<<<(BB * TT * AA + 255) / 256, 256>>>(actions);
    }

    // act_pre = actions @ W_as2 + b_as
    {
        GProb p = mkprob(pactpad, 64, 512, 1, pw_as2, 64,
                         b_as, nullptr, 0, pactpre, HH, nullptr, 0, 0);
        tgemm<<<dim3(8, (unsigned)(BT / 128)), 256>>>(p, p, 8);
    }
    // qpre = obs @ W_q1[R:,:] + b_q1
    {
        GProb p = mkprob(pobs, 2 * EE, EE, 48, pw_q1o, 3072,
                         b_q1, nullptr, 0, pqpre, HH, nullptr, 0, 0);
        tgemm<<<dim3(8, (unsigned)(BT / 128)), 256>>>(p, p, 8);
    }

    // x(0) || gh(0)
    {
        GProb px0 = mkprob(pposts, 128, 64, 3, pw_as1, 192,
                           nullptr, pactpre, TT * HH, nullptr, 0, pxs, HH, 1);
        GProb pg0 = mkprob(pbels, 2 * RR, RR, 24, pw_hh, 1536,
                           b_hh, nullptr, 0, pgh, 3 * RR, nullptr, 0, 0);
        tgemm<<<dim3(32, 16), 256>>>(px0, pg0, 8);
    }

    for (int t = 0; t < TT; ++t) {
        // gi (3 gates) + GRU fused
        gi_gru<<<dim3(8, 16), 256, 81920>>>(pxs, pw_ih, b_ih, o_bel, t);
        // gh(t+1) || h2(t)    (t=63: h2 only)
        {
            GProb ph2_ = mkprob(pbels, 2 * RR, RR, 24, pw_q1r, 1536,
                                nullptr, pqpre + (size_t)t * HH, TT * HH,
                                nullptr, 0, ph2s, HH, 1);
            if (t + 1 < TT) {
                GProb pgh_ = mkprob(pbels, 2 * RR, RR, 24, pw_hh, 1536,
                                    b_hh, nullptr, 0, pgh, 3 * RR, nullptr, 0, 0);
                tgemm<<<dim3(32, 16), 256>>>(pgh_, ph2_, 24);
            } else {
                tgemm<<<dim3(8, 16), 256>>>(ph2_, ph2_, 8);
            }
        }
        // q partials (split-K x4)
        {
            GProb p = mkprob(ph2s, 2 * HH, HH, 24, pw_q2, 1536,
                             nullptr, nullptr, 0, pqpart, 128, nullptr, 0, 0,
                             6, BB * 128);
            tgemm<<<dim3(2, 16, 4), 256>>>(p, p, 2);
        }
        // q reduce + dist + x(t+1)
        {
            const float* ap = pactpre + (size_t)((t + 1 < TT) ? (t + 1) : 0) * HH;
            qdx<<<dim3(8, 16), 256>>>(noise_q, b_q2, pw_as1, ap,
                                      o_qmean, o_qstd, o_post, t, (t + 1 < TT) ? 1 : 0);
        }
    }

    // deferred prior head over all B*T (h1_split aliases g_obs_split)
    {
        GProb p = mkprob(pbela, 2 * RR, RR, 24, pw_p1, 1536,
                         b_p1, nullptr, 0, nullptr, 0, pobs, HH, 1);
        tgemm<<<dim3(8, (unsigned)(BT / 128)), 256>>>(p, p, 8);
    }
    {
        GProb p = mkprob(pobs, 2 * HH, HH, 24, pw_p2, 1536,
                         b_p2, nullptr, 0, ppall, 2 * SS, nullptr, 0, 0);
        tgemm<<<dim3(2, (unsigned)(BT / 128)), 256>>>(p, p, 2);
    }
    dist_p_kernel<<<((unsigned)(BT * SS) + 255) / 256, 256>>>(noise_p, o_pmean, o_pstd, o_prior);
}